// round 8
// baseline (speedup 1.0000x reference)
#include <cuda_runtime.h>
#include <cuda_bf16.h>

// Problem constants
#define CELLS   4096
#define REGIONS 4096
#define NEMB    5
#define NINT    5

// Tiling: one wave at 5 blocks/SM * 148 SMs = 740; use 16 x 46 = 736 blocks
#define RT      256   // threads per block (1 region per thread)
#define CHUNK   4     // cell-rows staged per pipeline stage
#define YBLOCKS 46
#define NCHUNKS (CELLS / CHUNK)   // 1024 chunks of 4 cells

// floats per staged cell-row
#define ROW_F    (RT * NEMB)        // 1280 floats
#define ROW_F4   (ROW_F / 4)        // 320 float4
#define STAGE_F4 (CHUNK * ROW_F4)   // 1280 float4 per stage

typedef unsigned long long u64;

__device__ __forceinline__ unsigned smem_u32(const void* p) {
    unsigned a;
    asm("{ .reg .u64 t; cvta.to.shared.u64 t, %1; cvt.u32.u64 %0, t; }"
        : "=r"(a) : "l"(p));
    return a;
}

__device__ __forceinline__ u64 pack2(float lo, float hi) {
    u64 v;
    asm("mov.b64 %0, {%1, %2};" : "=l"(v) : "f"(lo), "f"(hi));
    return v;
}
__device__ __forceinline__ u64 bcast2(float x) {
    u64 v;
    asm("mov.b64 %0, {%1, %1};" : "=l"(v) : "f"(x));
    return v;
}
__device__ __forceinline__ void unpack2(u64 v, float& lo, float& hi) {
    asm("mov.b64 {%0, %1}, %2;" : "=f"(lo), "=f"(hi) : "l"(v));
}
__device__ __forceinline__ u64 ffma2(u64 a, u64 b, u64 c) {
    u64 d;
    asm("fma.rn.f32x2 %0, %1, %2, %3;" : "=l"(d) : "l"(a), "l"(b), "l"(c));
    return d;
}

__global__ __launch_bounds__(RT, 5)
void EmbeddingToExpression_45157286150935_kernel(
    const float* __restrict__ emb,    // [CELLS, REGIONS, NEMB]
    const int*   __restrict__ rix32,  // region_ix: int32 or int64 (detected)
    const float* __restrict__ w1,     // [N_REGIONS, NEMB, NINT]
    const float* __restrict__ b1,     // [N_REGIONS, NINT]
    const float* __restrict__ w2,     // [N_REGIONS, NINT, 1]
    const float* __restrict__ b2,     // [N_REGIONS, 1]
    float*       __restrict__ out)    // [CELLS, REGIONS]
{
    __shared__ float sh[2][CHUNK * ROW_F];   // 2 x 20 KB

    const int tid = threadIdx.x;
    const int r   = blockIdx.x * RT + tid;   // this thread's region (fixed)

    // this block's contiguous chunk range over the 1024 cell-chunks
    const int c0 = (int)(((long long)blockIdx.y      * NCHUNKS) / YBLOCKS);
    const int c1 = (int)(((long long)(blockIdx.y + 1) * NCHUNKS) / YBLOCKS);
    const int nk = c1 - c0;   // 22 or 23 stages

    // --- region_ix dtype detection: int64 values < 20000 -> odd words all 0
    const bool is64 = (rix32[1] == 0) & (rix32[3] == 0) &
                      (rix32[5] == 0) & (rix32[7] == 0);
    const int rix = is64 ? rix32[2 * r] : rix32[r];

    // --- gather + pre-transform per-region params (tables are L2-resident)
    // sigmoid(acc) = 0.5*tanh(0.5*acc) + 0.5; fold 0.5 into W1,B1.
    // o = B2 + sum_d sigmoid_d*W2_d = (B2 + 0.5*sum W2) + sum_d tanh(acc'_d)*(0.5*W2_d)
    u64   W1p[NEMB][2];   // {d0,d1},{d2,d3} pairs of 0.5*W1[e][d]
    float W1s[NEMB];      // 0.5*W1[e][4]
#pragma unroll
    for (int e = 0; e < NEMB; e++) {
        float a0 = 0.5f * __ldg(&w1[rix * 25 + e * 5 + 0]);
        float a1 = 0.5f * __ldg(&w1[rix * 25 + e * 5 + 1]);
        float a2 = 0.5f * __ldg(&w1[rix * 25 + e * 5 + 2]);
        float a3 = 0.5f * __ldg(&w1[rix * 25 + e * 5 + 3]);
        W1s[e]   = 0.5f * __ldg(&w1[rix * 25 + e * 5 + 4]);
        W1p[e][0] = pack2(a0, a1);
        W1p[e][1] = pack2(a2, a3);
    }
    u64 B1p0, B1p1; float B1s4;
    {
        float b0  = 0.5f * __ldg(&b1[rix * 5 + 0]);
        float bb1 = 0.5f * __ldg(&b1[rix * 5 + 1]);
        float b2v = 0.5f * __ldg(&b1[rix * 5 + 2]);
        float b3  = 0.5f * __ldg(&b1[rix * 5 + 3]);
        B1s4      = 0.5f * __ldg(&b1[rix * 5 + 4]);
        B1p0 = pack2(b0, bb1);
        B1p1 = pack2(b2v, b3);
    }
    float W2h[NINT];
    float o0 = __ldg(&b2[rix]);
#pragma unroll
    for (int d = 0; d < NINT; d++) {
        float w = __ldg(&w2[rix * NINT + d]);
        W2h[d] = 0.5f * w;
        o0    += 0.5f * w;
    }

    // float index of emb[0, region_tile_start, 0]; tile start 256-aligned ->
    // multiple of 1280 floats -> 16B aligned for cp.async 16.
    const size_t tile_base  = (size_t)blockIdx.x * RT * NEMB;
    const size_t row_stride = (size_t)REGIONS * NEMB;   // 20480 floats between cells

    // stage j (relative): copy CHUNK cell-rows of chunk (c0+j) into sh[j&1]
    auto stage = [&](int j) {
        unsigned sbase = smem_u32(&sh[j & 1][0]);
        const size_t chunk_base = tile_base + (size_t)(c0 + j) * CHUNK * row_stride;
#pragma unroll
        for (int i = 0; i < STAGE_F4 / RT; i++) {   // 5 cp.async.16 per thread
            int flat = i * RT + tid;                // 0..1279
            int row  = flat / ROW_F4;               // 0..3
            int col  = flat - row * ROW_F4;         // 0..319
            const float* g = emb + chunk_base
                           + (size_t)row * row_stride + (size_t)col * 4;
            unsigned s = sbase + (unsigned)flat * 16u;
            asm volatile("cp.async.ca.shared.global [%0], [%1], 16;"
                         :: "r"(s), "l"(g));
        }
        asm volatile("cp.async.commit_group;");
    };

    // --- software pipeline: depth-2 double buffer (R6 structure: issue next
    // stage BEFORE waiting, so requests are always in flight)
    stage(0);

#pragma unroll 1
    for (int j = 0; j < nk; j++) {
        const int cur = j & 1;
        if (j + 1 < nk) stage(j + 1);

        if (j + 1 < nk) asm volatile("cp.async.wait_group 1;");
        else            asm volatile("cp.async.wait_group 0;");
        __syncthreads();   // staged data visible to all threads

        const int a_base = (c0 + j) * CHUNK;
#pragma unroll
        for (int row = 0; row < CHUNK; row++) {
            const float* xs = &sh[cur][row * ROW_F + tid * NEMB]; // stride-5: conflict-free
            const float x0 = xs[0], x1 = xs[1], x2 = xs[2], x3 = xs[3], x4 = xs[4];

            // packed dot products: acc'_d = 0.5*(x . W1[:,d]) + 0.5*B1[d]
            u64 acc01 = B1p0, acc23 = B1p1;
            float acc4 = B1s4;
            {
                u64 xb;
                xb = bcast2(x0); acc01 = ffma2(xb, W1p[0][0], acc01); acc23 = ffma2(xb, W1p[0][1], acc23);
                acc4 = fmaf(x0, W1s[0], acc4);
                xb = bcast2(x1); acc01 = ffma2(xb, W1p[1][0], acc01); acc23 = ffma2(xb, W1p[1][1], acc23);
                acc4 = fmaf(x1, W1s[1], acc4);
                xb = bcast2(x2); acc01 = ffma2(xb, W1p[2][0], acc01); acc23 = ffma2(xb, W1p[2][1], acc23);
                acc4 = fmaf(x2, W1s[2], acc4);
                xb = bcast2(x3); acc01 = ffma2(xb, W1p[3][0], acc01); acc23 = ffma2(xb, W1p[3][1], acc23);
                acc4 = fmaf(x3, W1s[3], acc4);
                xb = bcast2(x4); acc01 = ffma2(xb, W1p[4][0], acc01); acc23 = ffma2(xb, W1p[4][1], acc23);
                acc4 = fmaf(x4, W1s[4], acc4);
            }
            float a0, a1, a2, a3;
            unpack2(acc01, a0, a1);
            unpack2(acc23, a2, a3);

            float t0, t1, t2, t3, t4;
            asm("tanh.approx.f32 %0, %1;" : "=f"(t0) : "f"(a0));
            asm("tanh.approx.f32 %0, %1;" : "=f"(t1) : "f"(a1));
            asm("tanh.approx.f32 %0, %1;" : "=f"(t2) : "f"(a2));
            asm("tanh.approx.f32 %0, %1;" : "=f"(t3) : "f"(a3));
            asm("tanh.approx.f32 %0, %1;" : "=f"(t4) : "f"(acc4));

            float o = o0;
            o = fmaf(t0, W2h[0], o);
            o = fmaf(t1, W2h[1], o);
            o = fmaf(t2, W2h[2], o);
            o = fmaf(t3, W2h[3], o);
            o = fmaf(t4, W2h[4], o);

            out[(size_t)(a_base + row) * REGIONS + r] = o;
        }
        __syncthreads();   // all reads of sh[cur] done before it is re-staged
    }
}

extern "C" void kernel_launch(void* const* d_in, const int* in_sizes, int n_in,
                              void* d_out, int out_size)
{
    const float* emb  = (const float*)d_in[0];
    const int*   rix  = (const int*)  d_in[1];
    const float* w1   = (const float*)d_in[2];
    const float* b1   = (const float*)d_in[3];
    const float* w2   = (const float*)d_in[4];
    const float* b2   = (const float*)d_in[5];
    float*       outp = (float*)d_out;

    dim3 grid(REGIONS / RT, YBLOCKS);   // (16, 46) = 736 blocks ~= one 5/SM wave
    EmbeddingToExpression_45157286150935_kernel<<<grid, RT>>>(
        emb, rix, w1, b1, w2, b2, outp);
}

// round 9
// speedup vs baseline: 1.9051x; 1.9051x over previous
#include <cuda_runtime.h>
#include <cuda_bf16.h>

// Problem constants
#define CELLS   4096
#define REGIONS 4096
#define NEMB    5
#define NINT    5

// Tiling: exactly one wave = 4 blocks/SM * 148 SMs = 592 blocks = 16 x 37
#define RT      256   // threads per block (1 region per thread)
#define CHUNK   4     // cell-rows staged per pipeline stage
#define YBLOCKS 37
#define NCHUNKS (CELLS / CHUNK)   // 1024 chunks of 4 cells
#define PD      3     // L2 prefetch distance (stages ahead)

// floats per staged cell-row
#define ROW_F    (RT * NEMB)        // 1280 floats
#define ROW_F4   (ROW_F / 4)        // 320 float4
#define STAGE_F4 (CHUNK * ROW_F4)   // 1280 float4 per stage
#define ROW_LINES   40              // 128B lines per cell-row (5120 B)
#define STAGE_LINES (CHUNK * ROW_LINES)   // 160 lines per stage

typedef unsigned long long u64;

__device__ __forceinline__ unsigned smem_u32(const void* p) {
    unsigned a;
    asm("{ .reg .u64 t; cvta.to.shared.u64 t, %1; cvt.u32.u64 %0, t; }"
        : "=r"(a) : "l"(p));
    return a;
}

__device__ __forceinline__ u64 pack2(float lo, float hi) {
    u64 v;
    asm("mov.b64 %0, {%1, %2};" : "=l"(v) : "f"(lo), "f"(hi));
    return v;
}
__device__ __forceinline__ u64 bcast2(float x) {
    u64 v;
    asm("mov.b64 %0, {%1, %1};" : "=l"(v) : "f"(x));
    return v;
}
__device__ __forceinline__ void unpack2(u64 v, float& lo, float& hi) {
    asm("mov.b64 {%0, %1}, %2;" : "=f"(lo), "=f"(hi) : "l"(v));
}
__device__ __forceinline__ u64 ffma2(u64 a, u64 b, u64 c) {
    u64 d;
    asm("fma.rn.f32x2 %0, %1, %2, %3;" : "=l"(d) : "l"(a), "l"(b), "l"(c));
    return d;
}

__global__ __launch_bounds__(RT, 4)
void EmbeddingToExpression_45157286150935_kernel(
    const float* __restrict__ emb,    // [CELLS, REGIONS, NEMB]
    const int*   __restrict__ rix32,  // region_ix: int32 or int64 (detected)
    const float* __restrict__ w1,     // [N_REGIONS, NEMB, NINT]
    const float* __restrict__ b1,     // [N_REGIONS, NINT]
    const float* __restrict__ w2,     // [N_REGIONS, NINT, 1]
    const float* __restrict__ b2,     // [N_REGIONS, 1]
    float*       __restrict__ out)    // [CELLS, REGIONS]
{
    __shared__ float sh[2][CHUNK * ROW_F];   // 2 x 20 KB

    const int tid = threadIdx.x;
    const int r   = blockIdx.x * RT + tid;   // this thread's region (fixed)

    // this block's contiguous chunk range over the 1024 cell-chunks
    const int c0 = (int)(((long long)blockIdx.y      * NCHUNKS) / YBLOCKS);
    const int c1 = (int)(((long long)(blockIdx.y + 1) * NCHUNKS) / YBLOCKS);
    const int nk = c1 - c0;   // 27 or 28 stages

    // --- region_ix dtype detection: int64 values < 20000 -> odd words all 0
    const bool is64 = (rix32[1] == 0) & (rix32[3] == 0) &
                      (rix32[5] == 0) & (rix32[7] == 0);
    const int rix = is64 ? rix32[2 * r] : rix32[r];

    // --- gather + pre-transform per-region params (tables are L2-resident)
    // sigmoid(acc) = 0.5*tanh(0.5*acc) + 0.5; fold 0.5 into W1,B1.
    // o = B2 + sum_d sigmoid_d*W2_d = (B2 + 0.5*sum W2) + sum_d tanh(acc'_d)*(0.5*W2_d)
    u64   W1p[NEMB][2];   // {d0,d1},{d2,d3} pairs of 0.5*W1[e][d]
    float W1s[NEMB];      // 0.5*W1[e][4]
#pragma unroll
    for (int e = 0; e < NEMB; e++) {
        float a0 = 0.5f * __ldg(&w1[rix * 25 + e * 5 + 0]);
        float a1 = 0.5f * __ldg(&w1[rix * 25 + e * 5 + 1]);
        float a2 = 0.5f * __ldg(&w1[rix * 25 + e * 5 + 2]);
        float a3 = 0.5f * __ldg(&w1[rix * 25 + e * 5 + 3]);
        W1s[e]   = 0.5f * __ldg(&w1[rix * 25 + e * 5 + 4]);
        W1p[e][0] = pack2(a0, a1);
        W1p[e][1] = pack2(a2, a3);
    }
    u64 B1p0, B1p1; float B1s4;
    {
        float b0  = 0.5f * __ldg(&b1[rix * 5 + 0]);
        float bb1 = 0.5f * __ldg(&b1[rix * 5 + 1]);
        float b2v = 0.5f * __ldg(&b1[rix * 5 + 2]);
        float b3  = 0.5f * __ldg(&b1[rix * 5 + 3]);
        B1s4      = 0.5f * __ldg(&b1[rix * 5 + 4]);
        B1p0 = pack2(b0, bb1);
        B1p1 = pack2(b2v, b3);
    }
    float W2h[NINT];
    float o0 = __ldg(&b2[rix]);
#pragma unroll
    for (int d = 0; d < NINT; d++) {
        float w = __ldg(&w2[rix * NINT + d]);
        W2h[d] = 0.5f * w;
        o0    += 0.5f * w;
    }

    // float index of emb[0, region_tile_start, 0]; tile start 256-aligned ->
    // multiple of 1280 floats -> 16B aligned for cp.async 16.
    const size_t tile_base  = (size_t)blockIdx.x * RT * NEMB;
    const size_t row_stride = (size_t)REGIONS * NEMB;   // 20480 floats between cells

    // stage j (relative): copy CHUNK cell-rows of chunk (c0+j) into sh[j&1]
    auto stage = [&](int j) {
        unsigned sbase = smem_u32(&sh[j & 1][0]);
        const size_t chunk_base = tile_base + (size_t)(c0 + j) * CHUNK * row_stride;
#pragma unroll
        for (int i = 0; i < STAGE_F4 / RT; i++) {   // 5 cp.async.16 per thread
            int flat = i * RT + tid;                // 0..1279
            int row  = flat / ROW_F4;               // 0..3
            int col  = flat - row * ROW_F4;         // 0..319
            const float* g = emb + chunk_base
                           + (size_t)row * row_stride + (size_t)col * 4;
            unsigned s = sbase + (unsigned)flat * 16u;
            asm volatile("cp.async.ca.shared.global [%0], [%1], 16;"
                         :: "r"(s), "l"(g));
        }
        asm volatile("cp.async.commit_group;");
    };

    // L2 prefetch of stage j (one 128B line per thread, 160 of 256 threads)
    auto l2pf = [&](int j) {
        if (tid < STAGE_LINES) {
            const size_t chunk_base = tile_base + (size_t)(c0 + j) * CHUNK * row_stride;
            int prow = tid / ROW_LINES;         // 0..3
            int pcol = tid - prow * ROW_LINES;  // 0..39
            const float* pg = emb + chunk_base
                            + (size_t)prow * row_stride + (size_t)pcol * 32;
            asm volatile("prefetch.global.L2 [%0];" :: "l"(pg));
        }
    };

    // --- software pipeline: depth-2 smem double buffer (R6 structure) plus an
    // L2 prefetch stream PD stages ahead (no registers, no smem, no barriers).
    l2pf(0); l2pf(1); l2pf(2);
    stage(0);

#pragma unroll 1
    for (int j = 0; j < nk; j++) {
        const int cur = j & 1;
        if (j + 1 < nk) stage(j + 1);
        if (j + PD < nk) l2pf(j + PD);   // keep HBM->L2 streaming ahead

        if (j + 1 < nk) asm volatile("cp.async.wait_group 1;");
        else            asm volatile("cp.async.wait_group 0;");
        __syncthreads();   // staged data visible to all threads

        const int a_base = (c0 + j) * CHUNK;
#pragma unroll
        for (int row = 0; row < CHUNK; row++) {
            const float* xs = &sh[cur][row * ROW_F + tid * NEMB]; // stride-5: conflict-free
            const float x0 = xs[0], x1 = xs[1], x2 = xs[2], x3 = xs[3], x4 = xs[4];

            // packed dot products: acc'_d = 0.5*(x . W1[:,d]) + 0.5*B1[d]
            u64 acc01 = B1p0, acc23 = B1p1;
            float acc4 = B1s4;
            {
                u64 xb;
                xb = bcast2(x0); acc01 = ffma2(xb, W1p[0][0], acc01); acc23 = ffma2(xb, W1p[0][1], acc23);
                acc4 = fmaf(x0, W1s[0], acc4);
                xb = bcast2(x1); acc01 = ffma2(xb, W1p[1][0], acc01); acc23 = ffma2(xb, W1p[1][1], acc23);
                acc4 = fmaf(x1, W1s[1], acc4);
                xb = bcast2(x2); acc01 = ffma2(xb, W1p[2][0], acc01); acc23 = ffma2(xb, W1p[2][1], acc23);
                acc4 = fmaf(x2, W1s[2], acc4);
                xb = bcast2(x3); acc01 = ffma2(xb, W1p[3][0], acc01); acc23 = ffma2(xb, W1p[3][1], acc23);
                acc4 = fmaf(x3, W1s[3], acc4);
                xb = bcast2(x4); acc01 = ffma2(xb, W1p[4][0], acc01); acc23 = ffma2(xb, W1p[4][1], acc23);
                acc4 = fmaf(x4, W1s[4], acc4);
            }
            float a0, a1, a2, a3;
            unpack2(acc01, a0, a1);
            unpack2(acc23, a2, a3);

            float t0, t1, t2, t3, t4;
            asm("tanh.approx.f32 %0, %1;" : "=f"(t0) : "f"(a0));
            asm("tanh.approx.f32 %0, %1;" : "=f"(t1) : "f"(a1));
            asm("tanh.approx.f32 %0, %1;" : "=f"(t2) : "f"(a2));
            asm("tanh.approx.f32 %0, %1;" : "=f"(t3) : "f"(a3));
            asm("tanh.approx.f32 %0, %1;" : "=f"(t4) : "f"(acc4));

            float o = o0;
            o = fmaf(t0, W2h[0], o);
            o = fmaf(t1, W2h[1], o);
            o = fmaf(t2, W2h[2], o);
            o = fmaf(t3, W2h[3], o);
            o = fmaf(t4, W2h[4], o);

            out[(size_t)(a_base + row) * REGIONS + r] = o;
        }
        __syncthreads();   // all reads of sh[cur] done before it is re-staged
    }
}

extern "C" void kernel_launch(void* const* d_in, const int* in_sizes, int n_in,
                              void* d_out, int out_size)
{
    const float* emb  = (const float*)d_in[0];
    const int*   rix  = (const int*)  d_in[1];
    const float* w1   = (const float*)d_in[2];
    const float* b1   = (const float*)d_in[3];
    const float* w2   = (const float*)d_in[4];
    const float* b2   = (const float*)d_in[5];
    float*       outp = (float*)d_out;

    dim3 grid(REGIONS / RT, YBLOCKS);   // (16, 37) = 592 blocks = one full wave
    EmbeddingToExpression_45157286150935_kernel<<<grid, RT>>>(
        emb, rix, w1, b1, w2, b2, outp);
}